// round 13
// baseline (speedup 1.0000x reference)
#include <cuda_runtime.h>
#include <cuda_fp16.h>
#include <cstdint>

#define NPTS 1048576
#define BSEG 2048
#define NCTA 148
#define NTHR 512

// smem byte offsets (all fp16; weights + acts)
//  W1: [128 o][64 k] SW128 (16KB)
//  W2, W3: 2 k-blocks of [128 o][64 k] (32KB each)
//  ACTF/ACTX: 2 act buffers, each 2 k-blocks of [256 rows][64 cols] fp16 (64KB each)
#define O_W1   0
#define O_W2   16384
#define O_W3   49152
#define O_ACTF 81920
#define O_ACTX 147456
#define O_SEGP 212992
#define O_POOL 213504
#define O_B2   214016
#define O_B3   214528
#define SMEM_BYTES 215040

#define AKB 32768   // act k-block stride (256 rows x 128B)
#define WKB 16384   // weight k-block stride (128 rows x 128B)

#define SWZ(x) ((uint32_t)(x) ^ ((((uint32_t)(x)) >> 3) & 0x70))

__device__ __forceinline__ uint32_t smem_u32(const void* p) {
    uint32_t a;
    asm("{ .reg .u64 t; cvta.to.shared.u64 t, %1; cvt.u32.u64 %0, t; }" : "=r"(a) : "l"(p));
    return a;
}
__device__ __forceinline__ void ldsm_x4(uint32_t addr, uint32_t r[4]) {
    asm volatile("ldmatrix.sync.aligned.m8n8.x4.shared.b16 {%0,%1,%2,%3}, [%4];"
        : "=r"(r[0]), "=r"(r[1]), "=r"(r[2]), "=r"(r[3]) : "r"(addr));
}
__device__ __forceinline__ void mma16816(float c[4], const uint32_t a[4], const uint32_t b0, const uint32_t b1) {
    asm volatile("mma.sync.aligned.m16n8k16.row.col.f32.f16.f16.f32 "
        "{%0,%1,%2,%3},{%4,%5,%6,%7},{%8,%9},{%0,%1,%2,%3};"
        : "+f"(c[0]), "+f"(c[1]), "+f"(c[2]), "+f"(c[3])
        : "r"(a[0]), "r"(a[1]), "r"(a[2]), "r"(a[3]), "r"(b0), "r"(b1));
}

// pack two floats -> one fp16x2 word (single F2FP instruction)
__device__ __forceinline__ uint32_t packh2(float v0, float v1) {
    __half2 h = __floats2half2_rn(v0, v1);
    return *(uint32_t*)&h;
}

// one layer, FULL 128 output cols per warp: acc[16 nt][4] += A[16 x K] * W[K x 128]
template<int KSTEPS>
__device__ __forceinline__ void run_layer(uint32_t aBase, uint32_t wBase,
                                          int rowbase, int lane, float acc[16][4])
{
    const int arow  = rowbase + (lane & 15);
    const int acol  = (lane >> 4) * 8;
    const int wrow  = ((lane >> 4) << 3) + (lane & 7);
    const int wcsel = ((lane >> 3) & 1) << 3;
#pragma unroll
    for (int s = 0; s < KSTEPS; s++) {
        const int kb = s >> 2, kk = (s & 3) * 16;
        uint32_t ah[4];
        ldsm_x4(aBase + (uint32_t)kb * AKB + SWZ(arow * 128 + (kk + acol) * 2), ah);
#pragma unroll
        for (int p8 = 0; p8 < 8; p8++) {
            uint32_t wh[4];
            ldsm_x4(wBase + (uint32_t)kb * WKB + SWZ((p8 * 16 + wrow) * 128 + (kk + wcsel) * 2), wh);
            mma16816(acc[p8 * 2],     ah, wh[0], wh[1]);
            mma16816(acc[p8 * 2 + 1], ah, wh[2], wh[3]);
        }
    }
}

// epilogue: bias + relu -> fp16 -> swizzled act buffer (warp-private 16 rows x 128 cols)
__device__ __forceinline__ void epi_store(char* sm_, uint32_t outOff,
                                          const float* bias, float acc[16][4],
                                          int rowbase, int lane)
{
    const int row = rowbase + (lane >> 2);
    const int c0  = 2 * (lane & 3);
#pragma unroll
    for (int nt = 0; nt < 16; nt++) {
        int col = nt * 8 + c0;
        float2 bb = *(const float2*)(bias + col);
        uint32_t kbb = (uint32_t)(col >> 6) * AKB;
        int kk = col & 63;
        *(uint32_t*)(sm_ + outOff + kbb + SWZ(row * 128 + kk * 2)) =
            packh2(fmaxf(acc[nt][0] + bb.x, 0.f), fmaxf(acc[nt][1] + bb.y, 0.f));
        *(uint32_t*)(sm_ + outOff + kbb + SWZ((row + 8) * 128 + kk * 2)) =
            packh2(fmaxf(acc[nt][2] + bb.x, 0.f), fmaxf(acc[nt][3] + bb.y, 0.f));
    }
}

// stage the warp's 16 feature rows (64 fp32 cols) into buffer k-block 0,
// in two 4xfloat4 batches to bound register pressure.
__device__ __forceinline__ void stage_feats(char* sm_, uint32_t bufOff, int rowbase, int lane,
                                            const float* __restrict__ feats, int n0, int hi)
{
    int r  = lane >> 1;
    int n  = n0 + r;
    int k0 = (lane & 1) * 32;
    int row = rowbase + r;
#pragma unroll
    for (int half = 0; half < 2; half++) {
        float4 f[4];
        if (n < hi) {
            const float4* src = (const float4*)(feats + (size_t)n * 64 + k0 + half * 16);
#pragma unroll
            for (int i = 0; i < 4; i++) f[i] = src[i];
        } else {
#pragma unroll
            for (int i = 0; i < 4; i++) f[i] = make_float4(0.f, 0.f, 0.f, 0.f);
        }
#pragma unroll
        for (int i = 0; i < 4; i++) {
            int k = k0 + half * 16 + 4 * i;
            *(uint32_t*)(sm_ + bufOff + SWZ(row * 128 + k * 2))       = packh2(f[i].x, f[i].y);
            *(uint32_t*)(sm_ + bufOff + SWZ(row * 128 + (k + 2) * 2)) = packh2(f[i].z, f[i].w);
        }
    }
}

__global__ void __launch_bounds__(NTHR, 1)
enc_kernel(const float* __restrict__ points, const float* __restrict__ features,
           const int* __restrict__ batch_words,
           const float* __restrict__ w_ne, const float* __restrict__ b_ne,
           const float* __restrict__ w1, const float* __restrict__ b1,
           const float* __restrict__ w2, const float* __restrict__ b2,
           const float* __restrict__ w3, const float* __restrict__ b3,
           const float* __restrict__ wg1, const float* __restrict__ bg1,
           const float* __restrict__ wg2, const float* __restrict__ bg2,
           const float* __restrict__ wg3, const float* __restrict__ bg3,
           float* __restrict__ out)
{
    extern __shared__ char sm[];
    const int tid = threadIdx.x, lane = tid & 31, wid = tid >> 5;
    const int rowbase = wid * 16;             // warp-private 16 rows (of 256/sweep)
    const uint32_t smb = smem_u32(sm);

    float* segp   = (float*)(sm + O_SEGP);
    int*   pooled = (int*)(sm + O_POOL);
    float* b2s    = (float*)(sm + O_B2);
    float* b3s    = (float*)(sm + O_B3);
    float* actf   = (float*)(sm + O_ACTF);    // pass-1 / head scratch alias

    // ---- stage weights fp16, transposed [o][k], SW128 k-blocks ----
    for (int idx = tid; idx < 8192; idx += NTHR) {         // W1 rows 32..95
        int k = idx >> 7, o = idx & 127;
        *(unsigned short*)(sm + O_W1 + SWZ(o * 128 + k * 2)) =
            __half_as_ushort(__float2half_rn(w1[(32 + k) * 128 + o]));
    }
    for (int idx = tid; idx < 16384; idx += NTHR) {
        int k = idx >> 7, o = idx & 127;
        uint32_t off = (uint32_t)(k >> 6) * WKB + SWZ(o * 128 + (k & 63) * 2);
        *(unsigned short*)(sm + O_W2 + off) = __half_as_ushort(__float2half_rn(w2[k * 128 + o]));
        *(unsigned short*)(sm + O_W3 + off) = __half_as_ushort(__float2half_rn(w3[k * 128 + o]));
    }
    if (tid < 128) { b2s[tid] = b2[tid]; b3s[tid] = b3[tid]; }
    __syncthreads();

    const int stride = (batch_words[NPTS - 1] == 0) ? 2 : 1;   // int64 vs int32

    const int s0 = (blockIdx.x * BSEG) / NCTA;
    const int s1 = ((blockIdx.x + 1) * BSEG) / NCTA;

    for (int b = s0; b < s1; b++) {
        int lo, hi;
        {
            int l = 0, h = NPTS;
            while (l < h) { int m = (l + h) >> 1; if (batch_words[m * stride] < b) l = m + 1; else h = m; }
            lo = l; h = NPTS;
            while (l < h) { int m = (l + h) >> 1; if (batch_words[m * stride] < b + 1) l = m + 1; else h = m; }
            hi = l;
        }

        // ---- pass 1: encoder + segmax -> seg_part ----
        if (tid < 128) pooled[tid] = 0;
        if (tid < 96)  actf[tid] = w_ne[tid];
        if (tid < 32)  actf[96 + tid] = b_ne[tid];
        __syncthreads();
        {
            float em[32];
#pragma unroll
            for (int j = 0; j < 32; j++) em[j] = 0.f;
            const float* wne = actf; const float* bne = actf + 96;
            for (int n = lo + tid; n < hi; n += NTHR) {
                float x = points[3 * n], y = points[3 * n + 1], z = points[3 * n + 2];
#pragma unroll
                for (int j = 0; j < 32; j++)
                    em[j] = fmaxf(em[j], bne[j] + x * wne[j] + y * wne[32 + j] + z * wne[64 + j]);
            }
#pragma unroll
            for (int j = 0; j < 32; j++) {
#pragma unroll
                for (int o = 16; o > 0; o >>= 1)
                    em[j] = fmaxf(em[j], __shfl_xor_sync(0xFFFFFFFFu, em[j], o));
            }
            if (lane == 0) {
#pragma unroll
                for (int j = 0; j < 32; j++) actf[128 + wid * 32 + j] = em[j];
            }
            __syncthreads();
            if (tid < 32) {
                float m = actf[128 + tid];
#pragma unroll
                for (int p = 1; p < 16; p++) m = fmaxf(m, actf[128 + p * 32 + tid]);
                actf[768 + tid] = m;
            }
            __syncthreads();
            if (tid < 128) {
                float s = b1[tid];
#pragma unroll
                for (int k = 0; k < 32; k++) s += actf[768 + k] * w1[k * 128 + tid];
                segp[tid] = s;
            }
            __syncthreads();
        }

        // ---- pass 2: 16 warp-private 16-row slices; no mainloop barriers ----
        __half2 rm[16];
#pragma unroll
        for (int j = 0; j < 16; j++) rm[j] = __floats2half2_rn(0.f, 0.f);

        uint32_t offF = O_ACTF, offX = O_ACTX;

        int n0 = lo + rowbase;
        if (n0 < hi) {
            stage_feats(sm, offF, rowbase, lane, features, n0, hi);
            __syncwarp();

            for (; n0 < hi; n0 += 256) {
                float acc[16][4];
                // layer 1: K=64, F(kb0) -> X, bias = seg_part
#pragma unroll
                for (int nt = 0; nt < 16; nt++)
                    acc[nt][0] = acc[nt][1] = acc[nt][2] = acc[nt][3] = 0.f;
                run_layer<4>(smb + offF, smb + O_W1, rowbase, lane, acc);
                epi_store(sm, offX, segp, acc, rowbase, lane);
                __syncwarp();

                // layer 2: K=128, X -> F, bias = b2
#pragma unroll
                for (int nt = 0; nt < 16; nt++)
                    acc[nt][0] = acc[nt][1] = acc[nt][2] = acc[nt][3] = 0.f;
                run_layer<8>(smb + offX, smb + O_W2, rowbase, lane, acc);
                epi_store(sm, offF, b2s, acc, rowbase, lane);
                __syncwarp();

                // stage NEXT sweep's features into X kb0 (X free after L2); overlaps L3
                stage_feats(sm, offX, rowbase, lane, features, n0 + 256, hi);

                // layer 3: K=128, reads F, bias = b3 -> masked running max (fp16 pairs)
#pragma unroll
                for (int nt = 0; nt < 16; nt++)
                    acc[nt][0] = acc[nt][1] = acc[nt][2] = acc[nt][3] = 0.f;
                run_layer<8>(smb + offF, smb + O_W3, rowbase, lane, acc);
                {
                    const int r0 = lane >> 2;
                    const int c0 = 2 * (lane & 3);
                    bool v0 = (n0 + r0) < hi;
                    bool v1 = (n0 + r0 + 8) < hi;
#pragma unroll
                    for (int nt = 0; nt < 16; nt++) {
                        int col = nt * 8 + c0;
                        float2 bb = *(const float2*)(b3s + col);
                        if (v0)
                            rm[nt] = __hmax2(rm[nt],
                                __floats2half2_rn(acc[nt][0] + bb.x, acc[nt][1] + bb.y));
                        if (v1)
                            rm[nt] = __hmax2(rm[nt],
                                __floats2half2_rn(acc[nt][2] + bb.x, acc[nt][3] + bb.y));
                    }
                }
                __syncwarp();
                uint32_t t = offF; offF = offX; offX = t;
            }
        }

        // ---- once per segment: reduce rm over the warp's 16 rows, then atomics ----
#pragma unroll
        for (int j = 0; j < 16; j++) {
#pragma unroll
            for (int o = 4; o < 32; o <<= 1) {
                uint32_t other = __shfl_xor_sync(0xFFFFFFFFu, *(uint32_t*)&rm[j], o);
                rm[j] = __hmax2(rm[j], *(__half2*)&other);
            }
        }
        if (lane < 4) {
#pragma unroll
            for (int nt = 0; nt < 16; nt++) {
                int col = nt * 8 + 2 * lane;
                float2 v = __half22float2(rm[nt]);
                atomicMax(&pooled[col],     __float_as_int(v.x));
                atomicMax(&pooled[col + 1], __float_as_int(v.y));
            }
        }
        __syncthreads();

        // ---- pass 3: head MLP 128 -> 128 -> 64 -> 32 ----
        if (tid < 128) {
            float s = bg1[tid];
#pragma unroll 8
            for (int k = 0; k < 128; k++) s += __int_as_float(pooled[k]) * wg1[k * 128 + tid];
            actf[tid] = fmaxf(s, 0.f);
        }
        __syncthreads();
        if (tid < 64) {
            float s = bg2[tid];
#pragma unroll 8
            for (int k = 0; k < 128; k++) s += actf[k] * wg2[k * 64 + tid];
            actf[128 + tid] = fmaxf(s, 0.f);
        }
        __syncthreads();
        if (tid < 32) {
            float s = bg3[tid];
#pragma unroll 8
            for (int k = 0; k < 64; k++) s += actf[128 + k] * wg3[k * 32 + tid];
            out[b * 32 + tid] = fmaxf(s, 0.f);
        }
        __syncthreads();
    }
}

extern "C" void kernel_launch(void* const* d_in, const int* in_sizes, int n_in,
                              void* d_out, int out_size)
{
    const float* points   = (const float*)d_in[0];
    const float* features = (const float*)d_in[1];
    const int*   batchw   = (const int*)  d_in[2];
    const float* w_ne = (const float*)d_in[3];
    const float* b_ne = (const float*)d_in[4];
    const float* w1   = (const float*)d_in[5];
    const float* b1   = (const float*)d_in[6];
    const float* w2   = (const float*)d_in[7];
    const float* b2   = (const float*)d_in[8];
    const float* w3   = (const float*)d_in[9];
    const float* b3   = (const float*)d_in[10];
    const float* wg1  = (const float*)d_in[11];
    const float* bg1  = (const float*)d_in[12];
    const float* wg2  = (const float*)d_in[13];
    const float* bg2  = (const float*)d_in[14];
    const float* wg3  = (const float*)d_in[15];
    const float* bg3  = (const float*)d_in[16];
    float* out = (float*)d_out;

    cudaFuncSetAttribute(enc_kernel, cudaFuncAttributeMaxDynamicSharedMemorySize, SMEM_BYTES);
    enc_kernel<<<NCTA, NTHR, SMEM_BYTES>>>(
        points, features, batchw,
        w_ne, b_ne, w1, b1, w2, b2, w3, b3,
        wg1, bg1, wg2, bg2, wg3, bg3, out);
}

// round 14
// speedup vs baseline: 1.2275x; 1.2275x over previous
#include <cuda_runtime.h>
#include <cuda_fp16.h>
#include <cstdint>

#define NPTS 1048576
#define BSEG 2048
#define NCTA 148
#define NTHR 256

// smem byte offsets (all fp16; weights + acts)
//  W1: [128 o][64 k] SW128 (16KB)
//  W2, W3: 2 k-blocks of [128 o][64 k] (32KB each)
//  ACTF/ACTX: 2 act buffers, each 2 k-blocks of [128 rows][64 cols] fp16 (32KB each)
#define O_W1   0
#define O_W2   16384
#define O_W3   49152
#define O_ACTF 81920
#define O_ACTX 114688
#define O_SEGP 147456
#define O_POOL 147968
#define O_B2   148480
#define O_B3   148992
#define SMEM_BYTES 149504

#define AKB 16384   // act k-block stride (128 rows x 128B)
#define WKB 16384   // weight k-block stride

#define SWZ(x) ((uint32_t)(x) ^ ((((uint32_t)(x)) >> 3) & 0x70))

__device__ __forceinline__ uint32_t smem_u32(const void* p) {
    uint32_t a;
    asm("{ .reg .u64 t; cvta.to.shared.u64 t, %1; cvt.u32.u64 %0, t; }" : "=r"(a) : "l"(p));
    return a;
}
__device__ __forceinline__ void ldsm_x4(uint32_t addr, uint32_t r[4]) {
    asm volatile("ldmatrix.sync.aligned.m8n8.x4.shared.b16 {%0,%1,%2,%3}, [%4];"
        : "=r"(r[0]), "=r"(r[1]), "=r"(r[2]), "=r"(r[3]) : "r"(addr));
}
__device__ __forceinline__ void mma16816(float c[4], const uint32_t a[4], const uint32_t b0, const uint32_t b1) {
    asm volatile("mma.sync.aligned.m16n8k16.row.col.f32.f16.f16.f32 "
        "{%0,%1,%2,%3},{%4,%5,%6,%7},{%8,%9},{%0,%1,%2,%3};"
        : "+f"(c[0]), "+f"(c[1]), "+f"(c[2]), "+f"(c[3])
        : "r"(a[0]), "r"(a[1]), "r"(a[2]), "r"(a[3]), "r"(b0), "r"(b1));
}

// pack two floats -> one fp16x2 word (single F2FP instruction)
__device__ __forceinline__ uint32_t packh2(float v0, float v1) {
    __half2 h = __floats2half2_rn(v0, v1);
    return *(uint32_t*)&h;
}

// one layer, FULL 128 output cols per warp: acc[16 nt][4] += A[16 x K] * W[K x 128].
// All 9 ldsm of a k-step are issued back-to-back (one latency window), then 16 MMAs.
template<int KSTEPS>
__device__ __forceinline__ void run_layer(uint32_t aBase, uint32_t wBase,
                                          int rowbase, int lane, float acc[16][4])
{
    const int arow  = rowbase + (lane & 15);
    const int acol  = (lane >> 4) * 8;
    const int wrow  = ((lane >> 4) << 3) + (lane & 7);
    const int wcsel = ((lane >> 3) & 1) << 3;
#pragma unroll
    for (int s = 0; s < KSTEPS; s++) {
        const int kb = s >> 2, kk = (s & 3) * 16;
        uint32_t ah[4], wh[8][4];
        ldsm_x4(aBase + (uint32_t)kb * AKB + SWZ(arow * 128 + (kk + acol) * 2), ah);
#pragma unroll
        for (int p8 = 0; p8 < 8; p8++)
            ldsm_x4(wBase + (uint32_t)kb * WKB + SWZ((p8 * 16 + wrow) * 128 + (kk + wcsel) * 2), wh[p8]);
#pragma unroll
        for (int p8 = 0; p8 < 8; p8++) {
            mma16816(acc[p8 * 2],     ah, wh[p8][0], wh[p8][1]);
            mma16816(acc[p8 * 2 + 1], ah, wh[p8][2], wh[p8][3]);
        }
    }
}

// epilogue: bias + relu -> fp16 -> swizzled act buffer (warp-private 16 rows x 128 cols)
__device__ __forceinline__ void epi_store(char* sm_, uint32_t outOff,
                                          const float* bias, float acc[16][4],
                                          int rowbase, int lane)
{
    const int row = rowbase + (lane >> 2);
    const int c0  = 2 * (lane & 3);
#pragma unroll
    for (int nt = 0; nt < 16; nt++) {
        int col = nt * 8 + c0;
        float2 bb = *(const float2*)(bias + col);
        uint32_t kbb = (uint32_t)(col >> 6) * AKB;
        int kk = col & 63;
        *(uint32_t*)(sm_ + outOff + kbb + SWZ(row * 128 + kk * 2)) =
            packh2(fmaxf(acc[nt][0] + bb.x, 0.f), fmaxf(acc[nt][1] + bb.y, 0.f));
        *(uint32_t*)(sm_ + outOff + kbb + SWZ((row + 8) * 128 + kk * 2)) =
            packh2(fmaxf(acc[nt][2] + bb.x, 0.f), fmaxf(acc[nt][3] + bb.y, 0.f));
    }
}

// LDG the warp's 16 feature rows into 8 float4 regs (latency hidden by later compute)
__device__ __forceinline__ void load_feats(float4 f[8], const float* __restrict__ feats,
                                           int n0, int hi, int lane)
{
    int n  = n0 + (lane >> 1);
    int k0 = (lane & 1) * 32;
    if (n < hi) {
        const float4* src = (const float4*)(feats + (size_t)n * 64 + k0);
#pragma unroll
        for (int i = 0; i < 8; i++) f[i] = src[i];
    } else {
#pragma unroll
        for (int i = 0; i < 8; i++) f[i] = make_float4(0.f, 0.f, 0.f, 0.f);
    }
}
// STS the prefetched rows into buffer k-block 0 (fp16, swizzled)
__device__ __forceinline__ void store_feats(char* sm_, uint32_t bufOff, int rowbase, int lane,
                                            const float4 f[8])
{
    int row = rowbase + (lane >> 1);
    int k0  = (lane & 1) * 32;
#pragma unroll
    for (int i = 0; i < 8; i++) {
        int k = k0 + 4 * i;
        *(uint32_t*)(sm_ + bufOff + SWZ(row * 128 + k * 2))       = packh2(f[i].x, f[i].y);
        *(uint32_t*)(sm_ + bufOff + SWZ(row * 128 + (k + 2) * 2)) = packh2(f[i].z, f[i].w);
    }
}

__global__ void __launch_bounds__(NTHR, 1)
enc_kernel(const float* __restrict__ points, const float* __restrict__ features,
           const int* __restrict__ batch_words,
           const float* __restrict__ w_ne, const float* __restrict__ b_ne,
           const float* __restrict__ w1, const float* __restrict__ b1,
           const float* __restrict__ w2, const float* __restrict__ b2,
           const float* __restrict__ w3, const float* __restrict__ b3,
           const float* __restrict__ wg1, const float* __restrict__ bg1,
           const float* __restrict__ wg2, const float* __restrict__ bg2,
           const float* __restrict__ wg3, const float* __restrict__ bg3,
           float* __restrict__ out)
{
    extern __shared__ char sm[];
    const int tid = threadIdx.x, lane = tid & 31, wid = tid >> 5;
    const int rowbase = wid * 16;             // warp-private 16 rows
    const uint32_t smb = smem_u32(sm);

    float* segp   = (float*)(sm + O_SEGP);
    int*   pooled = (int*)(sm + O_POOL);
    float* b2s    = (float*)(sm + O_B2);
    float* b3s    = (float*)(sm + O_B3);
    float* actf   = (float*)(sm + O_ACTF);    // pass-1 / head scratch alias

    // ---- stage weights fp16, transposed [o][k], SW128 k-blocks ----
    for (int idx = tid; idx < 8192; idx += NTHR) {         // W1 rows 32..95
        int k = idx >> 7, o = idx & 127;
        *(unsigned short*)(sm + O_W1 + SWZ(o * 128 + k * 2)) =
            __half_as_ushort(__float2half_rn(w1[(32 + k) * 128 + o]));
    }
    for (int idx = tid; idx < 16384; idx += NTHR) {
        int k = idx >> 7, o = idx & 127;
        uint32_t off = (uint32_t)(k >> 6) * WKB + SWZ(o * 128 + (k & 63) * 2);
        *(unsigned short*)(sm + O_W2 + off) = __half_as_ushort(__float2half_rn(w2[k * 128 + o]));
        *(unsigned short*)(sm + O_W3 + off) = __half_as_ushort(__float2half_rn(w3[k * 128 + o]));
    }
    if (tid < 128) { b2s[tid] = b2[tid]; b3s[tid] = b3[tid]; }
    __syncthreads();

    const int stride = (batch_words[NPTS - 1] == 0) ? 2 : 1;   // int64 vs int32

    const int s0 = (blockIdx.x * BSEG) / NCTA;
    const int s1 = ((blockIdx.x + 1) * BSEG) / NCTA;

    for (int b = s0; b < s1; b++) {
        int lo, hi;
        {
            int l = 0, h = NPTS;
            while (l < h) { int m = (l + h) >> 1; if (batch_words[m * stride] < b) l = m + 1; else h = m; }
            lo = l; h = NPTS;
            while (l < h) { int m = (l + h) >> 1; if (batch_words[m * stride] < b + 1) l = m + 1; else h = m; }
            hi = l;
        }

        // ---- pass 1: encoder + segmax -> seg_part ----
        if (tid < 128) pooled[tid] = 0;
        if (tid < 96)  actf[tid] = w_ne[tid];
        if (tid < 32)  actf[96 + tid] = b_ne[tid];
        __syncthreads();
        {
            float em[32];
#pragma unroll
            for (int j = 0; j < 32; j++) em[j] = 0.f;
            const float* wne = actf; const float* bne = actf + 96;
            for (int n = lo + tid; n < hi; n += NTHR) {
                float x = points[3 * n], y = points[3 * n + 1], z = points[3 * n + 2];
#pragma unroll
                for (int j = 0; j < 32; j++)
                    em[j] = fmaxf(em[j], bne[j] + x * wne[j] + y * wne[32 + j] + z * wne[64 + j]);
            }
#pragma unroll
            for (int j = 0; j < 32; j++) {
#pragma unroll
                for (int o = 16; o > 0; o >>= 1)
                    em[j] = fmaxf(em[j], __shfl_xor_sync(0xFFFFFFFFu, em[j], o));
            }
            if (lane == 0) {
#pragma unroll
                for (int j = 0; j < 32; j++) actf[128 + wid * 32 + j] = em[j];
            }
            __syncthreads();
            if (tid < 32) {
                float m = actf[128 + tid];
#pragma unroll
                for (int p = 1; p < 8; p++) m = fmaxf(m, actf[128 + p * 32 + tid]);
                actf[512 + tid] = m;
            }
            __syncthreads();
            if (tid < 128) {
                float s = b1[tid];
#pragma unroll
                for (int k = 0; k < 32; k++) s += actf[512 + k] * w1[k * 128 + tid];
                segp[tid] = s;
            }
            __syncthreads();
        }

        // ---- pass 2: warp-private 16-row slices; no mainloop barriers ----
        __half2 rm[16];
#pragma unroll
        for (int j = 0; j < 16; j++) rm[j] = __floats2half2_rn(0.f, 0.f);

        uint32_t offF = O_ACTF, offX = O_ACTX;

        int n0 = lo + rowbase;
        if (n0 < hi) {
            {
                float4 f[8];
                load_feats(f, features, n0, hi, lane);
                store_feats(sm, offF, rowbase, lane, f);
            }
            __syncwarp();

            for (; n0 < hi; n0 += 128) {
                // prefetch NEXT sweep's features into regs; LDG latency covered by L1+L2
                float4 f[8];
                load_feats(f, features, n0 + 128, hi, lane);

                float acc[16][4];
                // layer 1: K=64, F(kb0) -> X, bias = seg_part
#pragma unroll
                for (int nt = 0; nt < 16; nt++)
                    acc[nt][0] = acc[nt][1] = acc[nt][2] = acc[nt][3] = 0.f;
                run_layer<4>(smb + offF, smb + O_W1, rowbase, lane, acc);
                epi_store(sm, offX, segp, acc, rowbase, lane);
                __syncwarp();

                // layer 2: K=128, X -> F, bias = b2
#pragma unroll
                for (int nt = 0; nt < 16; nt++)
                    acc[nt][0] = acc[nt][1] = acc[nt][2] = acc[nt][3] = 0.f;
                run_layer<8>(smb + offX, smb + O_W2, rowbase, lane, acc);
                epi_store(sm, offF, b2s, acc, rowbase, lane);
                __syncwarp();

                // store next sweep's features into X kb0 (X free after L2); overlaps L3
                store_feats(sm, offX, rowbase, lane, f);

                // layer 3: K=128, reads F, bias = b3 -> masked running max (fp16 pairs)
#pragma unroll
                for (int nt = 0; nt < 16; nt++)
                    acc[nt][0] = acc[nt][1] = acc[nt][2] = acc[nt][3] = 0.f;
                run_layer<8>(smb + offF, smb + O_W3, rowbase, lane, acc);
                {
                    const int r0 = lane >> 2;
                    const int c0 = 2 * (lane & 3);
                    bool v0 = (n0 + r0) < hi;
                    bool v1 = (n0 + r0 + 8) < hi;
#pragma unroll
                    for (int nt = 0; nt < 16; nt++) {
                        int col = nt * 8 + c0;
                        float2 bb = *(const float2*)(b3s + col);
                        if (v0)
                            rm[nt] = __hmax2(rm[nt],
                                __floats2half2_rn(acc[nt][0] + bb.x, acc[nt][1] + bb.y));
                        if (v1)
                            rm[nt] = __hmax2(rm[nt],
                                __floats2half2_rn(acc[nt][2] + bb.x, acc[nt][3] + bb.y));
                    }
                }
                __syncwarp();
                uint32_t t = offF; offF = offX; offX = t;
            }
        }

        // ---- once per segment: reduce rm over the warp's 16 rows, then atomics ----
#pragma unroll
        for (int j = 0; j < 16; j++) {
#pragma unroll
            for (int o = 4; o < 32; o <<= 1) {
                uint32_t other = __shfl_xor_sync(0xFFFFFFFFu, *(uint32_t*)&rm[j], o);
                rm[j] = __hmax2(rm[j], *(__half2*)&other);
            }
        }
        if (lane < 4) {
#pragma unroll
            for (int nt = 0; nt < 16; nt++) {
                int col = nt * 8 + 2 * lane;
                float2 v = __half22float2(rm[nt]);
                atomicMax(&pooled[col],     __float_as_int(v.x));
                atomicMax(&pooled[col + 1], __float_as_int(v.y));
            }
        }
        __syncthreads();

        // ---- pass 3: head MLP 128 -> 128 -> 64 -> 32 ----
        if (tid < 128) {
            float s = bg1[tid];
#pragma unroll 8
            for (int k = 0; k < 128; k++) s += __int_as_float(pooled[k]) * wg1[k * 128 + tid];
            actf[tid] = fmaxf(s, 0.f);
        }
        __syncthreads();
        if (tid < 64) {
            float s = bg2[tid];
#pragma unroll 8
            for (int k = 0; k < 128; k++) s += actf[k] * wg2[k * 64 + tid];
            actf[128 + tid] = fmaxf(s, 0.f);
        }
        __syncthreads();
        if (tid < 32) {
            float s = bg3[tid];
#pragma unroll 8
            for (int k = 0; k < 64; k++) s += actf[128 + k] * wg3[k * 32 + tid];
            out[b * 32 + tid] = fmaxf(s, 0.f);
        }
        __syncthreads();
    }
}

extern "C" void kernel_launch(void* const* d_in, const int* in_sizes, int n_in,
                              void* d_out, int out_size)
{
    const float* points   = (const float*)d_in[0];
    const float* features = (const float*)d_in[1];
    const int*   batchw   = (const int*)  d_in[2];
    const float* w_ne = (const float*)d_in[3];
    const float* b_ne = (const float*)d_in[4];
    const float* w1   = (const float*)d_in[5];
    const float* b1   = (const float*)d_in[6];
    const float* w2   = (const float*)d_in[7];
    const float* b2   = (const float*)d_in[8];
    const float* w3   = (const float*)d_in[9];
    const float* b3   = (const float*)d_in[10];
    const float* wg1  = (const float*)d_in[11];
    const float* bg1  = (const float*)d_in[12];
    const float* wg2  = (const float*)d_in[13];
    const float* bg2  = (const float*)d_in[14];
    const float* wg3  = (const float*)d_in[15];
    const float* bg3  = (const float*)d_in[16];
    float* out = (float*)d_out;

    cudaFuncSetAttribute(enc_kernel, cudaFuncAttributeMaxDynamicSharedMemorySize, SMEM_BYTES);
    enc_kernel<<<NCTA, NTHR, SMEM_BYTES>>>(
        points, features, batchw,
        w_ne, b_ne, w1, b1, w2, b2, w3, b3,
        wg1, bg1, wg2, bg2, wg3, bg3, out);
}

// round 15
// speedup vs baseline: 1.2684x; 1.0333x over previous
#include <cuda_runtime.h>
#include <cuda_fp16.h>
#include <cstdint>

#define NPTS 1048576
#define BSEG 2048
#define NCTA 148
#define NTHR 384
#define NWARP 12
#define SWEEP 192   // rows per sweep = NWARP * 16

// smem byte offsets (all fp16; weights + acts)
//  W1: [128 o][64 k] SW128 (16KB)
//  W2, W3: 2 k-blocks of [128 o][64 k] (32KB each)
//  ACTF/ACTX: 2 act buffers, each 2 k-blocks of [192 rows][64 cols] fp16 (48KB each)
#define O_W1   0
#define O_W2   16384
#define O_W3   49152
#define O_ACTF 81920
#define O_ACTX 131072
#define O_SEGP 180224
#define O_POOL 180736
#define O_B2   181248
#define O_B3   181760
#define SMEM_BYTES 182272

#define AKB 24576   // act k-block stride (192 rows x 128B)
#define WKB 16384   // weight k-block stride

#define SWZ(x) ((uint32_t)(x) ^ ((((uint32_t)(x)) >> 3) & 0x70))

__device__ __forceinline__ uint32_t smem_u32(const void* p) {
    uint32_t a;
    asm("{ .reg .u64 t; cvta.to.shared.u64 t, %1; cvt.u32.u64 %0, t; }" : "=r"(a) : "l"(p));
    return a;
}
__device__ __forceinline__ void ldsm_x4(uint32_t addr, uint32_t r[4]) {
    asm volatile("ldmatrix.sync.aligned.m8n8.x4.shared.b16 {%0,%1,%2,%3}, [%4];"
        : "=r"(r[0]), "=r"(r[1]), "=r"(r[2]), "=r"(r[3]) : "r"(addr));
}
__device__ __forceinline__ void mma16816(float c[4], const uint32_t a[4], const uint32_t b0, const uint32_t b1) {
    asm volatile("mma.sync.aligned.m16n8k16.row.col.f32.f16.f16.f32 "
        "{%0,%1,%2,%3},{%4,%5,%6,%7},{%8,%9},{%0,%1,%2,%3};"
        : "+f"(c[0]), "+f"(c[1]), "+f"(c[2]), "+f"(c[3])
        : "r"(a[0]), "r"(a[1]), "r"(a[2]), "r"(a[3]), "r"(b0), "r"(b1));
}

// pack two floats -> one fp16x2 word (single F2FP instruction)
__device__ __forceinline__ uint32_t packh2(float v0, float v1) {
    __half2 h = __floats2half2_rn(v0, v1);
    return *(uint32_t*)&h;
}

// one layer, FULL 128 output cols per warp: acc[16 nt][4] += A[16 x K] * W[K x 128].
template<int KSTEPS>
__device__ __forceinline__ void run_layer(uint32_t aBase, uint32_t wBase,
                                          int rowbase, int lane, float acc[16][4])
{
    const int arow  = rowbase + (lane & 15);
    const int acol  = (lane >> 4) * 8;
    const int wrow  = ((lane >> 4) << 3) + (lane & 7);
    const int wcsel = ((lane >> 3) & 1) << 3;
#pragma unroll
    for (int s = 0; s < KSTEPS; s++) {
        const int kb = s >> 2, kk = (s & 3) * 16;
        uint32_t ah[4], wh[8][4];
        ldsm_x4(aBase + (uint32_t)kb * AKB + SWZ(arow * 128 + (kk + acol) * 2), ah);
#pragma unroll
        for (int p8 = 0; p8 < 8; p8++)
            ldsm_x4(wBase + (uint32_t)kb * WKB + SWZ((p8 * 16 + wrow) * 128 + (kk + wcsel) * 2), wh[p8]);
#pragma unroll
        for (int p8 = 0; p8 < 8; p8++) {
            mma16816(acc[p8 * 2],     ah, wh[p8][0], wh[p8][1]);
            mma16816(acc[p8 * 2 + 1], ah, wh[p8][2], wh[p8][3]);
        }
    }
}

// epilogue: bias + relu -> fp16 -> swizzled act buffer (warp-private 16 rows x 128 cols)
__device__ __forceinline__ void epi_store(char* sm_, uint32_t outOff,
                                          const float* bias, float acc[16][4],
                                          int rowbase, int lane)
{
    const int row = rowbase + (lane >> 2);
    const int c0  = 2 * (lane & 3);
#pragma unroll
    for (int nt = 0; nt < 16; nt++) {
        int col = nt * 8 + c0;
        float2 bb = *(const float2*)(bias + col);
        uint32_t kbb = (uint32_t)(col >> 6) * AKB;
        int kk = col & 63;
        *(uint32_t*)(sm_ + outOff + kbb + SWZ(row * 128 + kk * 2)) =
            packh2(fmaxf(acc[nt][0] + bb.x, 0.f), fmaxf(acc[nt][1] + bb.y, 0.f));
        *(uint32_t*)(sm_ + outOff + kbb + SWZ((row + 8) * 128 + kk * 2)) =
            packh2(fmaxf(acc[nt][2] + bb.x, 0.f), fmaxf(acc[nt][3] + bb.y, 0.f));
    }
}

// LDG the warp's 16 feature rows into 8 float4 regs
__device__ __forceinline__ void load_feats(float4 f[8], const float* __restrict__ feats,
                                           int n0, int hi, int lane)
{
    int n  = n0 + (lane >> 1);
    int k0 = (lane & 1) * 32;
    if (n < hi) {
        const float4* src = (const float4*)(feats + (size_t)n * 64 + k0);
#pragma unroll
        for (int i = 0; i < 8; i++) f[i] = src[i];
    } else {
#pragma unroll
        for (int i = 0; i < 8; i++) f[i] = make_float4(0.f, 0.f, 0.f, 0.f);
    }
}
// STS the prefetched rows into buffer k-block 0 (fp16, swizzled)
__device__ __forceinline__ void store_feats(char* sm_, uint32_t bufOff, int rowbase, int lane,
                                            const float4 f[8])
{
    int row = rowbase + (lane >> 1);
    int k0  = (lane & 1) * 32;
#pragma unroll
    for (int i = 0; i < 8; i++) {
        int k = k0 + 4 * i;
        *(uint32_t*)(sm_ + bufOff + SWZ(row * 128 + k * 2))       = packh2(f[i].x, f[i].y);
        *(uint32_t*)(sm_ + bufOff + SWZ(row * 128 + (k + 2) * 2)) = packh2(f[i].z, f[i].w);
    }
}

__global__ void __launch_bounds__(NTHR, 1)
enc_kernel(const float* __restrict__ points, const float* __restrict__ features,
           const int* __restrict__ batch_words,
           const float* __restrict__ w_ne, const float* __restrict__ b_ne,
           const float* __restrict__ w1, const float* __restrict__ b1,
           const float* __restrict__ w2, const float* __restrict__ b2,
           const float* __restrict__ w3, const float* __restrict__ b3,
           const float* __restrict__ wg1, const float* __restrict__ bg1,
           const float* __restrict__ wg2, const float* __restrict__ bg2,
           const float* __restrict__ wg3, const float* __restrict__ bg3,
           float* __restrict__ out)
{
    extern __shared__ char sm[];
    const int tid = threadIdx.x, lane = tid & 31, wid = tid >> 5;
    const int rowbase = wid * 16;             // warp-private 16 rows (of 192/sweep)
    const uint32_t smb = smem_u32(sm);

    float* segp   = (float*)(sm + O_SEGP);
    int*   pooled = (int*)(sm + O_POOL);
    float* b2s    = (float*)(sm + O_B2);
    float* b3s    = (float*)(sm + O_B3);
    float* actf   = (float*)(sm + O_ACTF);    // pass-1 / head scratch alias

    // ---- stage weights fp16, transposed [o][k], SW128 k-blocks ----
    for (int idx = tid; idx < 8192; idx += NTHR) {         // W1 rows 32..95
        int k = idx >> 7, o = idx & 127;
        *(unsigned short*)(sm + O_W1 + SWZ(o * 128 + k * 2)) =
            __half_as_ushort(__float2half_rn(w1[(32 + k) * 128 + o]));
    }
    for (int idx = tid; idx < 16384; idx += NTHR) {
        int k = idx >> 7, o = idx & 127;
        uint32_t off = (uint32_t)(k >> 6) * WKB + SWZ(o * 128 + (k & 63) * 2);
        *(unsigned short*)(sm + O_W2 + off) = __half_as_ushort(__float2half_rn(w2[k * 128 + o]));
        *(unsigned short*)(sm + O_W3 + off) = __half_as_ushort(__float2half_rn(w3[k * 128 + o]));
    }
    if (tid < 128) { b2s[tid] = b2[tid]; b3s[tid] = b3[tid]; }
    __syncthreads();

    const int stride = (batch_words[NPTS - 1] == 0) ? 2 : 1;   // int64 vs int32

    const int s0 = (blockIdx.x * BSEG) / NCTA;
    const int s1 = ((blockIdx.x + 1) * BSEG) / NCTA;

    for (int b = s0; b < s1; b++) {
        int lo, hi;
        {
            int l = 0, h = NPTS;
            while (l < h) { int m = (l + h) >> 1; if (batch_words[m * stride] < b) l = m + 1; else h = m; }
            lo = l; h = NPTS;
            while (l < h) { int m = (l + h) >> 1; if (batch_words[m * stride] < b + 1) l = m + 1; else h = m; }
            hi = l;
        }

        // ---- pass 1: encoder + segmax -> seg_part ----
        if (tid < 128) pooled[tid] = 0;
        if (tid < 96)  actf[tid] = w_ne[tid];
        if (tid < 32)  actf[96 + tid] = b_ne[tid];
        __syncthreads();
        {
            float em[32];
#pragma unroll
            for (int j = 0; j < 32; j++) em[j] = 0.f;
            const float* wne = actf; const float* bne = actf + 96;
            for (int n = lo + tid; n < hi; n += NTHR) {
                float x = points[3 * n], y = points[3 * n + 1], z = points[3 * n + 2];
#pragma unroll
                for (int j = 0; j < 32; j++)
                    em[j] = fmaxf(em[j], bne[j] + x * wne[j] + y * wne[32 + j] + z * wne[64 + j]);
            }
#pragma unroll
            for (int j = 0; j < 32; j++) {
#pragma unroll
                for (int o = 16; o > 0; o >>= 1)
                    em[j] = fmaxf(em[j], __shfl_xor_sync(0xFFFFFFFFu, em[j], o));
            }
            if (lane == 0) {
#pragma unroll
                for (int j = 0; j < 32; j++) actf[128 + wid * 32 + j] = em[j];
            }
            __syncthreads();
            if (tid < 32) {
                float m = actf[128 + tid];
#pragma unroll
                for (int p = 1; p < NWARP; p++) m = fmaxf(m, actf[128 + p * 32 + tid]);
                actf[640 + tid] = m;
            }
            __syncthreads();
            if (tid < 128) {
                float s = b1[tid];
#pragma unroll
                for (int k = 0; k < 32; k++) s += actf[640 + k] * w1[k * 128 + tid];
                segp[tid] = s;
            }
            __syncthreads();
        }

        // ---- pass 2: 12 warp-private 16-row slices; no mainloop barriers ----
        __half2 rm[16];
#pragma unroll
        for (int j = 0; j < 16; j++) rm[j] = __floats2half2_rn(0.f, 0.f);

        uint32_t offF = O_ACTF, offX = O_ACTX;

        int n0 = lo + rowbase;
        if (n0 < hi) {
            {
                float4 f[8];
                load_feats(f, features, n0, hi, lane);
                store_feats(sm, offF, rowbase, lane, f);
            }
            __syncwarp();

            for (; n0 < hi; n0 += SWEEP) {
                float acc[16][4];
                // layer 1: K=64, F(kb0) -> X, bias = seg_part
#pragma unroll
                for (int nt = 0; nt < 16; nt++)
                    acc[nt][0] = acc[nt][1] = acc[nt][2] = acc[nt][3] = 0.f;
                run_layer<4>(smb + offF, smb + O_W1, rowbase, lane, acc);
                epi_store(sm, offX, segp, acc, rowbase, lane);
                __syncwarp();

                // prefetch NEXT sweep's features (live only across L2; hidden by L2 compute)
                float4 f[8];
                load_feats(f, features, n0 + SWEEP, hi, lane);

                // layer 2: K=128, X -> F, bias = b2
#pragma unroll
                for (int nt = 0; nt < 16; nt++)
                    acc[nt][0] = acc[nt][1] = acc[nt][2] = acc[nt][3] = 0.f;
                run_layer<8>(smb + offX, smb + O_W2, rowbase, lane, acc);
                epi_store(sm, offF, b2s, acc, rowbase, lane);
                __syncwarp();

                // store next sweep's features into X kb0 (X free after L2); overlaps L3
                store_feats(sm, offX, rowbase, lane, f);

                // layer 3: K=128, reads F, bias = b3 -> masked running max (fp16 pairs)
#pragma unroll
                for (int nt = 0; nt < 16; nt++)
                    acc[nt][0] = acc[nt][1] = acc[nt][2] = acc[nt][3] = 0.f;
                run_layer<8>(smb + offF, smb + O_W3, rowbase, lane, acc);
                {
                    const int r0 = lane >> 2;
                    const int c0 = 2 * (lane & 3);
                    bool v0 = (n0 + r0) < hi;
                    bool v1 = (n0 + r0 + 8) < hi;
#pragma unroll
                    for (int nt = 0; nt < 16; nt++) {
                        int col = nt * 8 + c0;
                        float2 bb = *(const float2*)(b3s + col);
                        if (v0)
                            rm[nt] = __hmax2(rm[nt],
                                __floats2half2_rn(acc[nt][0] + bb.x, acc[nt][1] + bb.y));
                        if (v1)
                            rm[nt] = __hmax2(rm[nt],
                                __floats2half2_rn(acc[nt][2] + bb.x, acc[nt][3] + bb.y));
                    }
                }
                __syncwarp();
                uint32_t t = offF; offF = offX; offX = t;
            }
        }

        // ---- once per segment: reduce rm over the warp's 16 rows, then atomics ----
#pragma unroll
        for (int j = 0; j < 16; j++) {
#pragma unroll
            for (int o = 4; o < 32; o <<= 1) {
                uint32_t other = __shfl_xor_sync(0xFFFFFFFFu, *(uint32_t*)&rm[j], o);
                rm[j] = __hmax2(rm[j], *(__half2*)&other);
            }
        }
        if (lane < 4) {
#pragma unroll
            for (int nt = 0; nt < 16; nt++) {
                int col = nt * 8 + 2 * lane;
                float2 v = __half22float2(rm[nt]);
                atomicMax(&pooled[col],     __float_as_int(v.x));
                atomicMax(&pooled[col + 1], __float_as_int(v.y));
            }
        }
        __syncthreads();

        // ---- pass 3: head MLP 128 -> 128 -> 64 -> 32 ----
        if (tid < 128) {
            float s = bg1[tid];
#pragma unroll 8
            for (int k = 0; k < 128; k++) s += __int_as_float(pooled[k]) * wg1[k * 128 + tid];
            actf[tid] = fmaxf(s, 0.f);
        }
        __syncthreads();
        if (tid < 64) {
            float s = bg2[tid];
#pragma unroll 8
            for (int k = 0; k < 128; k++) s += actf[k] * wg2[k * 64 + tid];
            actf[128 + tid] = fmaxf(s, 0.f);
        }
        __syncthreads();
        if (tid < 32) {
            float s = bg3[tid];
#pragma unroll 8
            for (int k = 0; k < 64; k++) s += actf[128 + k] * wg3[k * 32 + tid];
            out[b * 32 + tid] = fmaxf(s, 0.f);
        }
        __syncthreads();
    }
}

extern "C" void kernel_launch(void* const* d_in, const int* in_sizes, int n_in,
                              void* d_out, int out_size)
{
    const float* points   = (const float*)d_in[0];
    const float* features = (const float*)d_in[1];
    const int*   batchw   = (const int*)  d_in[2];
    const float* w_ne = (const float*)d_in[3];
    const float* b_ne = (const float*)d_in[4];
    const float* w1   = (const float*)d_in[5];
    const float* b1   = (const float*)d_in[6];
    const float* w2   = (const float*)d_in[7];
    const float* b2   = (const float*)d_in[8];
    const float* w3   = (const float*)d_in[9];
    const float* b3   = (const float*)d_in[10];
    const float* wg1  = (const float*)d_in[11];
    const float* bg1  = (const float*)d_in[12];
    const float* wg2  = (const float*)d_in[13];
    const float* bg2  = (const float*)d_in[14];
    const float* wg3  = (const float*)d_in[15];
    const float* bg3  = (const float*)d_in[16];
    float* out = (float*)d_out;

    cudaFuncSetAttribute(enc_kernel, cudaFuncAttributeMaxDynamicSharedMemorySize, SMEM_BYTES);
    enc_kernel<<<NCTA, NTHR, SMEM_BYTES>>>(
        points, features, batchw,
        w_ne, b_ne, w1, b1, w2, b2, w3, b3,
        wg1, bg1, wg2, bg2, wg3, bg3, out);
}